// round 1
// baseline (speedup 1.0000x reference)
#include <cuda_runtime.h>
#include <cuda_bf16.h>

// Problem dims (fixed by reference)
#define BQ    4
#define SQ    2048
#define DM    1024
#define HID   4096
#define NH    16
#define DH    64
#define DIL   2
#define LQ    (SQ / DIL)          // 1024
#define MTOK  (BQ * SQ)           // 8192 tokens (also B*d*L)

// ---------------- scratch (static device globals; no runtime allocation) ----
__device__ float g_q   [(size_t)MTOK * DM];
__device__ float g_k   [(size_t)MTOK * DM];
__device__ float g_v   [(size_t)MTOK * DM];
__device__ float g_ctx [(size_t)MTOK * DM];
__device__ float g_res1[(size_t)MTOK * DM];
__device__ float g_fin [(size_t)MTOK * DM];
__device__ float g_h   [(size_t)MTOK * HID];
__device__ float g_res2[(size_t)MTOK * DM];

// ---------------- SGEMM: C[M,N] = A[M,K] @ B[K,N] + bias (+R / relu) --------
#define BM 128
#define BN 128
#define BK 16
#define TM 8
#define TN 8
// MODE 0: C = acc + bias
// MODE 1: C = acc + bias + R   (residual add, R is [M,N])
// MODE 2: C = relu(acc + bias)
template <int MODE>
__global__ void __launch_bounds__(256, 2)
sgemm_kernel(const float* __restrict__ A, const float* __restrict__ B,
             const float* __restrict__ bias, const float* __restrict__ R,
             float* __restrict__ C, int M, int N, int K)
{
    __shared__ float As[BK][BM + 4];
    __shared__ float Bs[BK][BN];

    const int tid  = threadIdx.x;
    const int bm   = blockIdx.y;
    const int bn   = blockIdx.x;
    const int trow = tid >> 4;     // 0..15
    const int tcol = tid & 15;     // 0..15

    const float* Ablk = A + (size_t)bm * BM * K;

    float acc[TM][TN];
#pragma unroll
    for (int i = 0; i < TM; i++)
#pragma unroll
        for (int j = 0; j < TN; j++) acc[i][j] = 0.f;

    for (int kb = 0; kb < K; kb += BK) {
        // A tile: 128 rows x 16 cols = 512 float4, 2 per thread, store transposed
#pragma unroll
        for (int t = 0; t < 2; t++) {
            int p   = tid + t * 256;
            int row = p >> 2;
            int c4  = p & 3;
            float4 av = *(const float4*)(Ablk + (size_t)row * K + kb + c4 * 4);
            As[c4 * 4 + 0][row] = av.x;
            As[c4 * 4 + 1][row] = av.y;
            As[c4 * 4 + 2][row] = av.z;
            As[c4 * 4 + 3][row] = av.w;
        }
        // B tile: 16 rows x 128 cols = 512 float4, 2 per thread
#pragma unroll
        for (int t = 0; t < 2; t++) {
            int p   = tid + t * 256;
            int row = p >> 5;
            int c4  = p & 31;
            *(float4*)(&Bs[row][c4 * 4]) =
                *(const float4*)(B + (size_t)(kb + row) * N + bn * BN + c4 * 4);
        }
        __syncthreads();

#pragma unroll
        for (int k = 0; k < BK; k++) {
            float af[TM], bf[TN];
#pragma unroll
            for (int i = 0; i < TM; i++) af[i] = As[k][trow * TM + i];
#pragma unroll
            for (int j = 0; j < TN; j++) bf[j] = Bs[k][tcol * TN + j];
#pragma unroll
            for (int i = 0; i < TM; i++)
#pragma unroll
                for (int j = 0; j < TN; j++)
                    acc[i][j] = fmaf(af[i], bf[j], acc[i][j]);
        }
        __syncthreads();
    }

    const int crow0 = bm * BM + trow * TM;
    const int ccol0 = bn * BN + tcol * TN;
#pragma unroll
    for (int i = 0; i < TM; i++) {
        size_t roff = (size_t)(crow0 + i) * N + ccol0;
#pragma unroll
        for (int j = 0; j < TN; j++) {
            float v = acc[i][j] + bias[ccol0 + j];
            if (MODE == 1) v += R[roff + j];
            if (MODE == 2) v = fmaxf(v, 0.f);
            C[roff + j] = v;
        }
    }
}

// ---------------- Flash attention over dilated groups -----------------------
// grid: x = g*NH + h (128), y = q-tile of 128 rows (8). block = 128 threads.
// Each thread owns one query row; K/V processed in 64-row smem tiles.
__global__ void __launch_bounds__(128)
flash_kernel(const float* __restrict__ q_tok, const float* __restrict__ k_tok,
             const float* __restrict__ v_tok, float* __restrict__ ctx_tok)
{
    __shared__ float sbuf[2 * 64 * DH];     // sK | sV, 32 KB
    float* sK = sbuf;
    float* sV = sbuf + 64 * DH;

    const int gh  = blockIdx.x;
    const int qt  = blockIdx.y;
    const int g   = gh >> 4;
    const int h   = gh & 15;
    const int b   = g >> 1;
    const int di  = g & 1;
    const int tid = threadIdx.x;
    const int l0  = qt * 128;

    // load my query row (token layout; dilated index)
    const int tq = b * SQ + 2 * (l0 + tid) + di;
    float qreg[DH];
    {
        const float4* qp = (const float4*)(q_tok + (size_t)tq * DM + h * DH);
#pragma unroll
        for (int c4 = 0; c4 < DH / 4; c4++) {
            float4 qv = qp[c4];
            qreg[c4 * 4 + 0] = qv.x; qreg[c4 * 4 + 1] = qv.y;
            qreg[c4 * 4 + 2] = qv.z; qreg[c4 * 4 + 3] = qv.w;
        }
    }

    float mrun = -1e30f, lsum = 0.f;
    float accv[DH];
#pragma unroll
    for (int c = 0; c < DH; c++) accv[c] = 0.f;

    for (int kt = 0; kt < LQ / 64; kt++) {       // 16 tiles of 64 keys
        // cooperative coalesced load of K,V tiles (64 rows x 64 cols)
        for (int p = tid; p < 64 * (DH / 4); p += 128) {
            int r  = p >> 4;
            int c4 = p & 15;
            int t  = b * SQ + 2 * (kt * 64 + r) + di;
            ((float4*)sK)[p] = ((const float4*)(k_tok + (size_t)t * DM + h * DH))[c4];
            ((float4*)sV)[p] = ((const float4*)(v_tok + (size_t)t * DM + h * DH))[c4];
        }
        __syncthreads();

        for (int j = 0; j < 64; j++) {
            const float4* kj = (const float4*)(sK + j * DH);
            float s0 = 0.f, s1 = 0.f, s2 = 0.f, s3 = 0.f;
#pragma unroll
            for (int c4 = 0; c4 < DH / 4; c4++) {
                float4 kv = kj[c4];
                s0 = fmaf(qreg[c4 * 4 + 0], kv.x, s0);
                s1 = fmaf(qreg[c4 * 4 + 1], kv.y, s1);
                s2 = fmaf(qreg[c4 * 4 + 2], kv.z, s2);
                s3 = fmaf(qreg[c4 * 4 + 3], kv.w, s3);
            }
            float s = ((s0 + s1) + (s2 + s3)) * 0.125f;   // 1/sqrt(64)

            if (s > mrun) {                                // rare rescale
                float corr = __expf(mrun - s);
                lsum *= corr;
#pragma unroll
                for (int c = 0; c < DH; c++) accv[c] *= corr;
                mrun = s;
            }
            float p = __expf(s - mrun);
            lsum += p;
            const float4* vj = (const float4*)(sV + j * DH);
#pragma unroll
            for (int c4 = 0; c4 < DH / 4; c4++) {
                float4 vv = vj[c4];
                accv[c4 * 4 + 0] = fmaf(p, vv.x, accv[c4 * 4 + 0]);
                accv[c4 * 4 + 1] = fmaf(p, vv.y, accv[c4 * 4 + 1]);
                accv[c4 * 4 + 2] = fmaf(p, vv.z, accv[c4 * 4 + 2]);
                accv[c4 * 4 + 3] = fmaf(p, vv.w, accv[c4 * 4 + 3]);
            }
        }
        __syncthreads();
    }

    // write context (token layout, same dilated mapping)
    const float inv = 1.f / lsum;
    float4* op = (float4*)(ctx_tok + (size_t)tq * DM + h * DH);
#pragma unroll
    for (int c4 = 0; c4 < DH / 4; c4++) {
        float4 ov;
        ov.x = accv[c4 * 4 + 0] * inv;
        ov.y = accv[c4 * 4 + 1] * inv;
        ov.z = accv[c4 * 4 + 2] * inv;
        ov.w = accv[c4 * 4 + 3] * inv;
        op[c4] = ov;
    }
}

// ---------------- LayerNorm over last dim (1024), one block per row ---------
__global__ void __launch_bounds__(256)
ln_kernel(const float* __restrict__ X, const float* __restrict__ gam,
          const float* __restrict__ bet, float* __restrict__ Y)
{
    __shared__ float red[16];
    const int row = blockIdx.x;
    const int tid = threadIdx.x;

    float4 v = ((const float4*)(X + (size_t)row * DM))[tid];
    float s = v.x + v.y + v.z + v.w;
    float q = v.x * v.x + v.y * v.y + v.z * v.z + v.w * v.w;

#pragma unroll
    for (int o = 16; o; o >>= 1) {
        s += __shfl_down_sync(0xffffffffu, s, o);
        q += __shfl_down_sync(0xffffffffu, q, o);
    }
    if ((tid & 31) == 0) { red[tid >> 5] = s; red[8 + (tid >> 5)] = q; }
    __syncthreads();
    if (tid < 32) {
        float ss = (tid < 8) ? red[tid] : 0.f;
        float qq = (tid < 8) ? red[8 + tid] : 0.f;
#pragma unroll
        for (int o = 4; o; o >>= 1) {
            ss += __shfl_down_sync(0xffffffffu, ss, o);
            qq += __shfl_down_sync(0xffffffffu, qq, o);
        }
        if (tid == 0) { red[0] = ss; red[1] = qq; }
    }
    __syncthreads();

    const float mu   = red[0] * (1.f / DM);
    const float var  = red[1] * (1.f / DM) - mu * mu;
    const float rstd = rsqrtf(var + 1e-5f);

    float4 gv = ((const float4*)gam)[tid];
    float4 bv = ((const float4*)bet)[tid];
    float4 o;
    o.x = (v.x - mu) * rstd * gv.x + bv.x;
    o.y = (v.y - mu) * rstd * gv.y + bv.y;
    o.z = (v.z - mu) * rstd * gv.z + bv.z;
    o.w = (v.w - mu) * rstd * gv.w + bv.w;
    ((float4*)(Y + (size_t)row * DM))[tid] = o;
}

// ---------------- launch ----------------------------------------------------
extern "C" void kernel_launch(void* const* d_in, const int* in_sizes, int n_in,
                              void* d_out, int out_size)
{
    const float* x     = (const float*)d_in[0];
    const float* Wq    = (const float*)d_in[1];
    const float* bq    = (const float*)d_in[2];
    const float* Wk    = (const float*)d_in[3];
    const float* bk    = (const float*)d_in[4];
    const float* Wv    = (const float*)d_in[5];
    const float* bv    = (const float*)d_in[6];
    const float* Wo    = (const float*)d_in[7];
    const float* bo    = (const float*)d_in[8];
    const float* ln1_g = (const float*)d_in[9];
    const float* ln1_b = (const float*)d_in[10];
    const float* W1    = (const float*)d_in[11];
    const float* b1    = (const float*)d_in[12];
    const float* W2    = (const float*)d_in[13];
    const float* b2    = (const float*)d_in[14];
    const float* ln2_g = (const float*)d_in[15];
    const float* ln2_b = (const float*)d_in[16];
    float* out = (float*)d_out;

    float *q, *k, *v, *ctx, *res1, *fin, *hbuf, *res2;
    cudaGetSymbolAddress((void**)&q,    g_q);
    cudaGetSymbolAddress((void**)&k,    g_k);
    cudaGetSymbolAddress((void**)&v,    g_v);
    cudaGetSymbolAddress((void**)&ctx,  g_ctx);
    cudaGetSymbolAddress((void**)&res1, g_res1);
    cudaGetSymbolAddress((void**)&fin,  g_fin);
    cudaGetSymbolAddress((void**)&hbuf, g_h);
    cudaGetSymbolAddress((void**)&res2, g_res2);

    dim3 blk(256);
    dim3 gD(DM / BN, MTOK / BM);    // (8, 64)
    dim3 gH(HID / BN, MTOK / BM);   // (32, 64)

    // QKV projections (token layout; dilation handled in attention indexing)
    sgemm_kernel<0><<<gD, blk>>>(x, Wq, bq, nullptr, q, MTOK, DM, DM);
    sgemm_kernel<0><<<gD, blk>>>(x, Wk, bk, nullptr, k, MTOK, DM, DM);
    sgemm_kernel<0><<<gD, blk>>>(x, Wv, bv, nullptr, v, MTOK, DM, DM);

    // attention
    flash_kernel<<<dim3(BQ * DIL * NH, LQ / 128), 128>>>(q, k, v, ctx);

    // output projection + residual
    sgemm_kernel<1><<<gD, blk>>>(ctx, Wo, bo, x, res1, MTOK, DM, DM);
    ln_kernel<<<MTOK, 256>>>(res1, ln1_g, ln1_b, fin);

    // FFN
    sgemm_kernel<2><<<gH, blk>>>(fin, W1, b1, nullptr, hbuf, MTOK, HID, DM);
    sgemm_kernel<1><<<gD, blk>>>(hbuf, W2, b2, fin, res2, MTOK, DM, HID);
    ln_kernel<<<MTOK, 256>>>(res2, ln2_g, ln2_b, out);
}

// round 4
// speedup vs baseline: 1.6756x; 1.6756x over previous
#include <cuda_runtime.h>
#include <cuda_bf16.h>
#include <cstdint>

// Problem dims (fixed by reference)
#define BQ    4
#define SQ    2048
#define DM    1024
#define HID   4096
#define NH    16
#define DH    64
#define DIL   2
#define LQ    (SQ / DIL)          // 1024
#define MTOK  (BQ * SQ)           // 8192 tokens

// ---------------- scratch (static device globals) ---------------------------
__device__ float g_q   [(size_t)MTOK * DM];
__device__ float g_k   [(size_t)MTOK * DM];
__device__ float g_v   [(size_t)MTOK * DM];
__device__ float g_ctx [(size_t)MTOK * DM];
__device__ float g_res1[(size_t)MTOK * DM];
__device__ float g_fin [(size_t)MTOK * DM];
__device__ float g_res2[(size_t)MTOK * DM];
__device__ __nv_bfloat16 g_hh[(size_t)MTOK * HID];   // relu(h) hi
__device__ __nv_bfloat16 g_hl[(size_t)MTOK * HID];   // relu(h) lo

// ---------------- helpers ----------------------------------------------------
__device__ __forceinline__ uint32_t s2u(const void* p) {
    uint32_t a;
    asm("{ .reg .u64 t; cvta.to.shared.u64 t, %1; cvt.u32.u64 %0, t; }" : "=r"(a) : "l"(p));
    return a;
}

__device__ __forceinline__ uint32_t packbf2(float a, float b) {
    __nv_bfloat162 t;
    t.x = __float2bfloat16(a);
    t.y = __float2bfloat16(b);
    return *(uint32_t*)&t;
}

__device__ __forceinline__ void mma16816(float* d, const uint32_t* a, const uint32_t* b) {
    asm volatile(
        "mma.sync.aligned.m16n8k16.row.col.f32.bf16.bf16.f32 "
        "{%0,%1,%2,%3}, {%4,%5,%6,%7}, {%8,%9}, {%0,%1,%2,%3};"
        : "+f"(d[0]), "+f"(d[1]), "+f"(d[2]), "+f"(d[3])
        : "r"(a[0]), "r"(a[1]), "r"(a[2]), "r"(a[3]), "r"(b[0]), "r"(b[1]));
}

__device__ __forceinline__ void ldsm4(uint32_t* r, uint32_t addr) {
    asm volatile("ldmatrix.sync.aligned.m8n8.x4.shared.b16 {%0,%1,%2,%3}, [%4];"
                 : "=r"(r[0]), "=r"(r[1]), "=r"(r[2]), "=r"(r[3]) : "r"(addr));
}

__device__ __forceinline__ void ldsm4t(uint32_t* r, uint32_t addr) {
    asm volatile("ldmatrix.sync.aligned.m8n8.x4.trans.shared.b16 {%0,%1,%2,%3}, [%4];"
                 : "=r"(r[0]), "=r"(r[1]), "=r"(r[2]), "=r"(r[3]) : "r"(addr));
}

// ---------------- bf16x3 HMMA GEMM -------------------------------------------
// C[M,N] = A[M,Kd] @ W[Kd,N] (+bias, +R / relu)
// A: fp32 (split in-kernel) or pre-split bf16 hi/lo (ABF16)
// MODE 0: +bias   MODE 1: +bias+R   MODE 2: relu(+bias)
// OUTBF16: write hi/lo bf16 instead of fp32
#define KT   32
#define PA   40                    // A smem pitch (bf16)
#define PB   136                   // B smem pitch (bf16)
#define ASZ  (128 * PA * 2)        // 10240 B per A tile
#define BSZ  (KT * PB * 2)         // 8704 B per B tile
#define STG  (2 * ASZ + 2 * BSZ)   // 37888 B per stage
#define DYN_SMEM (2 * STG)         // 75776 B

template <int MODE, bool ABF16, bool OUTBF16>
__global__ void __launch_bounds__(256, 1)
tgemm_kernel(const float* __restrict__ A32,
             const __nv_bfloat16* __restrict__ Abh, const __nv_bfloat16* __restrict__ Abl,
             const float* __restrict__ W, const float* __restrict__ bias,
             const float* __restrict__ Rres,
             float* __restrict__ C, __nv_bfloat16* __restrict__ Ch,
             __nv_bfloat16* __restrict__ Cl, int M, int N, int Kd)
{
    extern __shared__ __align__(16) char smem[];
    const uint32_t sb = s2u(smem);
    const int tid  = threadIdx.x;
    const int wid  = tid >> 5;
    const int lane = tid & 31;
    const int bm   = blockIdx.y;
    const int bn   = blockIdx.x;
    const int wm0  = (wid & 1) * 64;     // warp m origin within block tile
    const int wn0  = (wid >> 1) * 32;    // warp n origin

    // staging registers
    float4 stA[4];
    uint4  stA16[4];                     // ABF16: 2 for hi, 2 for lo
    float4 stB[4];

    // per-thread load coordinates
    const int ar  = tid >> 1;            // A row 0..127
    const int ak0 = (tid & 1) * 16;      // A k offset (16 floats per thread)
    const int bk  = tid >> 3;            // B k row 0..31
    const int bn0 = (tid & 7) * 16;      // B n offset (16 floats per thread)

    float acc[4][4][4];
#pragma unroll
    for (int i = 0; i < 4; i++)
#pragma unroll
        for (int j = 0; j < 4; j++)
#pragma unroll
            for (int l = 0; l < 4; l++) acc[i][j][l] = 0.f;

    const int nk = Kd / KT;

    auto load_regs = [&](int kb) {
        const int kbase = kb * KT;
        if (ABF16) {
#pragma unroll
            for (int i = 0; i < 2; i++) {
                stA16[i]     = *(const uint4*)(Abh + ((size_t)(bm * 128 + ar) * Kd + kbase + ak0 + i * 8));
                stA16[2 + i] = *(const uint4*)(Abl + ((size_t)(bm * 128 + ar) * Kd + kbase + ak0 + i * 8));
            }
        } else {
#pragma unroll
            for (int i = 0; i < 4; i++)
                stA[i] = *(const float4*)(A32 + (size_t)(bm * 128 + ar) * Kd + kbase + ak0 + i * 4);
        }
#pragma unroll
        for (int i = 0; i < 4; i++)
            stB[i] = *(const float4*)(W + (size_t)(kbase + bk) * N + bn * 128 + bn0 + i * 4);
    };

    auto store_smem = [&](int buf) {
        char* base = smem + buf * STG;
        __nv_bfloat16* sAh = (__nv_bfloat16*)(base);
        __nv_bfloat16* sAl = (__nv_bfloat16*)(base + ASZ);
        __nv_bfloat16* sBh = (__nv_bfloat16*)(base + 2 * ASZ);
        __nv_bfloat16* sBl = (__nv_bfloat16*)(base + 2 * ASZ + BSZ);
        if (ABF16) {
#pragma unroll
            for (int i = 0; i < 2; i++) {
                *(uint4*)(sAh + ar * PA + ak0 + i * 8) = stA16[i];
                *(uint4*)(sAl + ar * PA + ak0 + i * 8) = stA16[2 + i];
            }
        } else {
#pragma unroll
            for (int i = 0; i < 4; i++) {
                float4 v = stA[i];
                uint32_t h0 = packbf2(v.x, v.y);
                uint32_t h1 = packbf2(v.z, v.w);
                float hx = __bfloat162float(__float2bfloat16(v.x));
                float hy = __bfloat162float(__float2bfloat16(v.y));
                float hz = __bfloat162float(__float2bfloat16(v.z));
                float hw = __bfloat162float(__float2bfloat16(v.w));
                uint32_t l0 = packbf2(v.x - hx, v.y - hy);
                uint32_t l1 = packbf2(v.z - hz, v.w - hw);
                uint2 uh; uh.x = h0; uh.y = h1;
                uint2 ul; ul.x = l0; ul.y = l1;
                *(uint2*)(sAh + ar * PA + ak0 + i * 4) = uh;
                *(uint2*)(sAl + ar * PA + ak0 + i * 4) = ul;
            }
        }
#pragma unroll
        for (int i = 0; i < 4; i++) {
            float4 v = stB[i];
            uint32_t h0 = packbf2(v.x, v.y);
            uint32_t h1 = packbf2(v.z, v.w);
            float hx = __bfloat162float(__float2bfloat16(v.x));
            float hy = __bfloat162float(__float2bfloat16(v.y));
            float hz = __bfloat162float(__float2bfloat16(v.z));
            float hw = __bfloat162float(__float2bfloat16(v.w));
            uint32_t l0 = packbf2(v.x - hx, v.y - hy);
            uint32_t l1 = packbf2(v.z - hz, v.w - hw);
            uint2 uh; uh.x = h0; uh.y = h1;
            uint2 ul; ul.x = l0; ul.y = l1;
            *(uint2*)(sBh + bk * PB + bn0 + i * 4) = uh;
            *(uint2*)(sBl + bk * PB + bn0 + i * 4) = ul;
        }
    };

    auto compute = [&](int buf) {
        const uint32_t base = sb + buf * STG;
        const uint32_t aAh = base;
        const uint32_t aAl = base + ASZ;
        const uint32_t aBh = base + 2 * ASZ;
        const uint32_t aBl = base + 2 * ASZ + BSZ;
        const int lr = lane & 15;
        const int lc = (lane >> 4) * 8;
#pragma unroll
        for (int ks = 0; ks < KT; ks += 16) {
            uint32_t ah[4][4], al[4][4], bh[2][4], bl[2][4];
#pragma unroll
            for (int mt = 0; mt < 4; mt++) {
                uint32_t off = ((wm0 + mt * 16 + lr) * PA + ks + lc) * 2;
                ldsm4(ah[mt], aAh + off);
                ldsm4(al[mt], aAl + off);
            }
#pragma unroll
            for (int g = 0; g < 2; g++) {
                uint32_t off = ((ks + lr) * PB + wn0 + g * 16 + lc) * 2;
                ldsm4t(bh[g], aBh + off);
                ldsm4t(bl[g], aBl + off);
            }
#pragma unroll
            for (int mt = 0; mt < 4; mt++)
#pragma unroll
                for (int nt = 0; nt < 4; nt++) {
                    const int g = nt >> 1, q = (nt & 1) * 2;
                    uint32_t bbh[2] = { bh[g][q], bh[g][q + 1] };
                    uint32_t bbl[2] = { bl[g][q], bl[g][q + 1] };
                    mma16816(acc[mt][nt], ah[mt], bbh);
                    mma16816(acc[mt][nt], ah[mt], bbl);
                    mma16816(acc[mt][nt], al[mt], bbh);
                }
        }
    };

    // pipeline
    load_regs(0);
    store_smem(0);
    __syncthreads();
    for (int kb = 0; kb < nk; kb++) {
        if (kb + 1 < nk) load_regs(kb + 1);
        compute(kb & 1);
        if (kb + 1 < nk) store_smem((kb + 1) & 1);
        __syncthreads();
    }

    // epilogue
    const int rbase = bm * 128 + wm0 + (lane >> 2);
    const int cbase = bn * 128 + wn0 + (lane & 3) * 2;
#pragma unroll
    for (int mt = 0; mt < 4; mt++) {
#pragma unroll
        for (int half = 0; half < 2; half++) {
            const int row = rbase + mt * 16 + half * 8;
#pragma unroll
            for (int nt = 0; nt < 4; nt++) {
                const int col = cbase + nt * 8;
                float v0 = acc[mt][nt][half * 2 + 0] + bias[col];
                float v1 = acc[mt][nt][half * 2 + 1] + bias[col + 1];
                if (MODE == 1) {
                    v0 += Rres[(size_t)row * N + col];
                    v1 += Rres[(size_t)row * N + col + 1];
                }
                if (MODE == 2) { v0 = fmaxf(v0, 0.f); v1 = fmaxf(v1, 0.f); }
                if (OUTBF16) {
                    uint32_t h = packbf2(v0, v1);
                    float h0 = __bfloat162float(__float2bfloat16(v0));
                    float h1 = __bfloat162float(__float2bfloat16(v1));
                    uint32_t l = packbf2(v0 - h0, v1 - h1);
                    *(uint32_t*)(Ch + (size_t)row * N + col) = h;
                    *(uint32_t*)(Cl + (size_t)row * N + col) = l;
                } else {
                    float2 o; o.x = v0; o.y = v1;
                    *(float2*)(C + (size_t)row * N + col) = o;
                }
            }
        }
    }
}

// ---------------- Flash attention over dilated groups ------------------------
__global__ void __launch_bounds__(128)
flash_kernel(const float* __restrict__ q_tok, const float* __restrict__ k_tok,
             const float* __restrict__ v_tok, float* __restrict__ ctx_tok)
{
    __shared__ float sbuf[2 * 64 * DH];
    float* sK = sbuf;
    float* sV = sbuf + 64 * DH;

    const int gh  = blockIdx.x;
    const int qt  = blockIdx.y;
    const int g   = gh >> 4;
    const int h   = gh & 15;
    const int b   = g >> 1;
    const int di  = g & 1;
    const int tid = threadIdx.x;
    const int l0  = qt * 128;

    const int tq = b * SQ + 2 * (l0 + tid) + di;
    float qreg[DH];
    {
        const float4* qp = (const float4*)(q_tok + (size_t)tq * DM + h * DH);
#pragma unroll
        for (int c4 = 0; c4 < DH / 4; c4++) {
            float4 qv = qp[c4];
            qreg[c4 * 4 + 0] = qv.x; qreg[c4 * 4 + 1] = qv.y;
            qreg[c4 * 4 + 2] = qv.z; qreg[c4 * 4 + 3] = qv.w;
        }
    }

    float mrun = -1e30f, lsum = 0.f;
    float accv[DH];
#pragma unroll
    for (int c = 0; c < DH; c++) accv[c] = 0.f;

    for (int kt = 0; kt < LQ / 64; kt++) {
        for (int p = tid; p < 64 * (DH / 4); p += 128) {
            int r  = p >> 4;
            int c4 = p & 15;
            int t  = b * SQ + 2 * (kt * 64 + r) + di;
            ((float4*)sK)[p] = ((const float4*)(k_tok + (size_t)t * DM + h * DH))[c4];
            ((float4*)sV)[p] = ((const float4*)(v_tok + (size_t)t * DM + h * DH))[c4];
        }
        __syncthreads();

        for (int j = 0; j < 64; j++) {
            const float4* kj = (const float4*)(sK + j * DH);
            float s0 = 0.f, s1 = 0.f, s2 = 0.f, s3 = 0.f;
#pragma unroll
            for (int c4 = 0; c4 < DH / 4; c4++) {
                float4 kv = kj[c4];
                s0 = fmaf(qreg[c4 * 4 + 0], kv.x, s0);
                s1 = fmaf(qreg[c4 * 4 + 1], kv.y, s1);
                s2 = fmaf(qreg[c4 * 4 + 2], kv.z, s2);
                s3 = fmaf(qreg[c4 * 4 + 3], kv.w, s3);
            }
            float s = ((s0 + s1) + (s2 + s3)) * 0.125f;

            if (s > mrun) {
                float corr = __expf(mrun - s);
                lsum *= corr;
#pragma unroll
                for (int c = 0; c < DH; c++) accv[c] *= corr;
                mrun = s;
            }
            float p = __expf(s - mrun);
            lsum += p;
            const float4* vj = (const float4*)(sV + j * DH);
#pragma unroll
            for (int c4 = 0; c4 < DH / 4; c4++) {
                float4 vv = vj[c4];
                accv[c4 * 4 + 0] = fmaf(p, vv.x, accv[c4 * 4 + 0]);
                accv[c4 * 4 + 1] = fmaf(p, vv.y, accv[c4 * 4 + 1]);
                accv[c4 * 4 + 2] = fmaf(p, vv.z, accv[c4 * 4 + 2]);
                accv[c4 * 4 + 3] = fmaf(p, vv.w, accv[c4 * 4 + 3]);
            }
        }
        __syncthreads();
    }

    const float inv = 1.f / lsum;
    float4* op = (float4*)(ctx_tok + (size_t)tq * DM + h * DH);
#pragma unroll
    for (int c4 = 0; c4 < DH / 4; c4++) {
        float4 ov;
        ov.x = accv[c4 * 4 + 0] * inv;
        ov.y = accv[c4 * 4 + 1] * inv;
        ov.z = accv[c4 * 4 + 2] * inv;
        ov.w = accv[c4 * 4 + 3] * inv;
        op[c4] = ov;
    }
}

// ---------------- LayerNorm ---------------------------------------------------
__global__ void __launch_bounds__(256)
ln_kernel(const float* __restrict__ X, const float* __restrict__ gam,
          const float* __restrict__ bet, float* __restrict__ Y)
{
    __shared__ float red[16];
    const int row = blockIdx.x;
    const int tid = threadIdx.x;

    float4 v = ((const float4*)(X + (size_t)row * DM))[tid];
    float s = v.x + v.y + v.z + v.w;
    float q = v.x * v.x + v.y * v.y + v.z * v.z + v.w * v.w;

#pragma unroll
    for (int o = 16; o; o >>= 1) {
        s += __shfl_down_sync(0xffffffffu, s, o);
        q += __shfl_down_sync(0xffffffffu, q, o);
    }
    if ((tid & 31) == 0) { red[tid >> 5] = s; red[8 + (tid >> 5)] = q; }
    __syncthreads();
    if (tid < 32) {
        float ss = (tid < 8) ? red[tid] : 0.f;
        float qq = (tid < 8) ? red[8 + tid] : 0.f;
#pragma unroll
        for (int o = 4; o; o >>= 1) {
            ss += __shfl_down_sync(0xffffffffu, ss, o);
            qq += __shfl_down_sync(0xffffffffu, qq, o);
        }
        if (tid == 0) { red[0] = ss; red[1] = qq; }
    }
    __syncthreads();

    const float mu   = red[0] * (1.f / DM);
    const float var  = red[1] * (1.f / DM) - mu * mu;
    const float rstd = rsqrtf(var + 1e-5f);

    float4 gv = ((const float4*)gam)[tid];
    float4 bv = ((const float4*)bet)[tid];
    float4 o;
    o.x = (v.x - mu) * rstd * gv.x + bv.x;
    o.y = (v.y - mu) * rstd * gv.y + bv.y;
    o.z = (v.z - mu) * rstd * gv.z + bv.z;
    o.w = (v.w - mu) * rstd * gv.w + bv.w;
    ((float4*)(Y + (size_t)row * DM))[tid] = o;
}

// ---------------- launch ------------------------------------------------------
extern "C" void kernel_launch(void* const* d_in, const int* in_sizes, int n_in,
                              void* d_out, int out_size)
{
    const float* x     = (const float*)d_in[0];
    const float* Wq    = (const float*)d_in[1];
    const float* bq    = (const float*)d_in[2];
    const float* Wk    = (const float*)d_in[3];
    const float* bk    = (const float*)d_in[4];
    const float* Wv    = (const float*)d_in[5];
    const float* bv    = (const float*)d_in[6];
    const float* Wo    = (const float*)d_in[7];
    const float* bo    = (const float*)d_in[8];
    const float* ln1_g = (const float*)d_in[9];
    const float* ln1_b = (const float*)d_in[10];
    const float* W1    = (const float*)d_in[11];
    const float* b1    = (const float*)d_in[12];
    const float* W2    = (const float*)d_in[13];
    const float* b2    = (const float*)d_in[14];
    const float* ln2_g = (const float*)d_in[15];
    const float* ln2_b = (const float*)d_in[16];
    float* out = (float*)d_out;

    float *q, *k, *v, *ctx, *res1, *fin, *res2;
    __nv_bfloat16 *hh, *hl;
    cudaGetSymbolAddress((void**)&q,    g_q);
    cudaGetSymbolAddress((void**)&k,    g_k);
    cudaGetSymbolAddress((void**)&v,    g_v);
    cudaGetSymbolAddress((void**)&ctx,  g_ctx);
    cudaGetSymbolAddress((void**)&res1, g_res1);
    cudaGetSymbolAddress((void**)&fin,  g_fin);
    cudaGetSymbolAddress((void**)&res2, g_res2);
    cudaGetSymbolAddress((void**)&hh,   g_hh);
    cudaGetSymbolAddress((void**)&hl,   g_hl);

    cudaFuncSetAttribute(tgemm_kernel<0, false, false>, cudaFuncAttributeMaxDynamicSharedMemorySize, DYN_SMEM);
    cudaFuncSetAttribute(tgemm_kernel<1, false, false>, cudaFuncAttributeMaxDynamicSharedMemorySize, DYN_SMEM);
    cudaFuncSetAttribute(tgemm_kernel<2, false, true >, cudaFuncAttributeMaxDynamicSharedMemorySize, DYN_SMEM);
    cudaFuncSetAttribute(tgemm_kernel<1, true,  false>, cudaFuncAttributeMaxDynamicSharedMemorySize, DYN_SMEM);

    dim3 gD(DM / 128, MTOK / 128);    // (8, 64)
    dim3 gH(HID / 128, MTOK / 128);   // (32, 64)

    // QKV projections (A = x fp32, split in-kernel)
    tgemm_kernel<0, false, false><<<gD, 256, DYN_SMEM>>>(x, nullptr, nullptr, Wq, bq, nullptr, q, nullptr, nullptr, MTOK, DM, DM);
    tgemm_kernel<0, false, false><<<gD, 256, DYN_SMEM>>>(x, nullptr, nullptr, Wk, bk, nullptr, k, nullptr, nullptr, MTOK, DM, DM);
    tgemm_kernel<0, false, false><<<gD, 256, DYN_SMEM>>>(x, nullptr, nullptr, Wv, bv, nullptr, v, nullptr, nullptr, MTOK, DM, DM);

    // attention
    flash_kernel<<<dim3(BQ * DIL * NH, LQ / 128), 128>>>(q, k, v, ctx);

    // output projection + residual + LN1
    tgemm_kernel<1, false, false><<<gD, 256, DYN_SMEM>>>(ctx, nullptr, nullptr, Wo, bo, x, res1, nullptr, nullptr, MTOK, DM, DM);
    ln_kernel<<<MTOK, 256>>>(res1, ln1_g, ln1_b, fin);

    // FFN1: h = relu(fin @ W1 + b1), emitted as bf16 hi/lo directly
    tgemm_kernel<2, false, true><<<gH, 256, DYN_SMEM>>>(fin, nullptr, nullptr, W1, b1, nullptr, nullptr, hh, hl, MTOK, HID, DM);
    // FFN2: res2 = h @ W2 + b2 + fin   (A = bf16 hi/lo)
    tgemm_kernel<1, true, false><<<gD, 256, DYN_SMEM>>>(nullptr, hh, hl, W2, b2, fin, res2, nullptr, nullptr, MTOK, DM, HID);
    ln_kernel<<<MTOK, 256>>>(res2, ln2_g, ln2_b, out);
}